// round 15
// baseline (speedup 1.0000x reference)
#include <cuda_runtime.h>
#include <cuda_fp16.h>
#include <math.h>
#include <stdint.h>

#define NN   262144
#define HH   256
#define NV   65536
#define NG   512
#define NP   8
#define NHID 64

#define NTILES    4096      // NN / 64
#define GRID_MAIN 148

// ---------------- device globals ----------------
__device__ float  g_sums[NG * HH];
__device__ float  g_maxs[NG * HH];
__device__ int    g_start[NG + 1];

// ---------------- helpers ----------------
__device__ __forceinline__ uint32_t smem_u32(const void* p) {
    uint32_t a;
    asm("{ .reg .u64 t; cvta.to.shared.u64 t, %1; cvt.u32.u64 %0, t; }" : "=r"(a) : "l"(p));
    return a;
}
__device__ __forceinline__ void cp16(uint32_t dst, const void* src) {
    asm volatile("cp.async.cg.shared.global [%0], [%1], 16;" :: "r"(dst), "l"(src));
}
__device__ __forceinline__ void atomicMaxF(float* addr, float v) {
    if (v >= 0.0f) atomicMax((int*)addr, __float_as_int(v));
    else           atomicMin((unsigned int*)addr, __float_as_uint(v));
}
#define LDMX4(r0,r1,r2,r3,addr) \
    asm volatile("ldmatrix.sync.aligned.m8n8.x4.shared.b16 {%0,%1,%2,%3}, [%4];" \
                 : "=r"(r0), "=r"(r1), "=r"(r2), "=r"(r3) : "r"(addr))
#define MMA16816(c0,c1,c2,c3,a0,a1,a2,a3,b0,b1) \
    asm volatile("mma.sync.aligned.m16n8k16.row.col.f32.f16.f16.f32 " \
                 "{%0,%1,%2,%3}, {%4,%5,%6,%7}, {%8,%9}, {%0,%1,%2,%3};" \
                 : "+f"(c0), "+f"(c1), "+f"(c2), "+f"(c3) \
                 : "r"(a0), "r"(a1), "r"(a2), "r"(a3), "r"(b0), "r"(b1))

// ---------------- main: persistent HMMA GEMM; contiguous tiles; carry epilogue ----------------
// smem layout (206848 B dynamic):
//   B:        [0, 135168)                256 rows x 264 halfs (stride 528 B)
//   A stages: [135168, 135168+2*33792)   2 x (64 rows x 264 halfs)
//   misc at 202752:
//     brow[2][64] int (512) | wrow[2][64] f (512) | sbias[256] f (1024) | sgate[448] f (1792)
#define A_OFF    135168
#define A_STAGE  33792
#define MISC_OFF 202752
#define SMEM_SZ  206848

__global__ __launch_bounds__(512, 1) void main_kernel(
    const float* __restrict__ emb,
    const int*   __restrict__ batch,
    const int*   __restrict__ ntype,
    const float* __restrict__ bpre,
    const float* __restrict__ Wpre,
    const float* __restrict__ props,
    const float* __restrict__ W1, const float* __restrict__ b1,
    const float* __restrict__ W2, const float* __restrict__ b2)
{
    extern __shared__ char sm[];
    const uint32_t sbase = smem_u32(sm);
    int*   brow  = (int*)  (sm + MISC_OFF);            // [2][64]
    float* wrow  = (float*)(sm + MISC_OFF + 512);      // [2][64]
    float* sbias = (float*)(sm + MISC_OFF + 1024);     // [256]
    float* sgate = (float*)(sm + MISC_OFF + 2048);     // [448]

    const int tid  = threadIdx.x;
    const int wid  = tid >> 5;
    const int lane = tid & 31;
    const int wm   = wid >> 2;     // 0..3: rows [wm*16, +16)
    const int wn   = wid & 3;      // 0..3: cols [wn*64, +64)
    const int b    = blockIdx.x;

    // contiguous tile range: blocks 0..99 get 28 tiles, 100..147 get 27
    const int tstart = b * 27 + min(b, 100);
    const int tcnt   = 27 + (b < 100 ? 1 : 0);

    // ---- phase A: B transpose+convert, gates, g_start scan, sbias, A(tstart) LDG ----

    // B: Wpre[k][n] -> Bs[n][k] fp16 (coalesced LDG.32 across n at fixed k)
    {
        const int bn  = tid & 255;       // output row n
        const int bk0 = (tid >> 8) * 128;
        const uint32_t bdst = sbase + (uint32_t)(bn * 528 + bk0 * 2);
        #pragma unroll
        for (int jj = 0; jj < 16; jj++) {
            float v[8];
            #pragma unroll
            for (int i = 0; i < 8; i++)
                v[i] = __ldg(&Wpre[(size_t)(bk0 + jj * 8 + i) * 256 + bn]);
            __half2 q0 = __float22half2_rn(make_float2(v[0], v[1]));
            __half2 q1 = __float22half2_rn(make_float2(v[2], v[3]));
            __half2 q2 = __float22half2_rn(make_float2(v[4], v[5]));
            __half2 q3 = __float22half2_rn(make_float2(v[6], v[7]));
            asm volatile("st.shared.v4.b32 [%0], {%1,%2,%3,%4};"
                         :: "r"(bdst + jj * 16),
                            "r"(*(uint32_t*)&q0), "r"(*(uint32_t*)&q1),
                            "r"(*(uint32_t*)&q2), "r"(*(uint32_t*)&q3) : "memory");
        }
    }

    // gates for this CTA's contiguous var range
    {
        if (tid < tcnt * 16) {
            const int var = tstart * 16 + tid;
            float4 p0 = __ldg((const float4*)props + var * 2);
            float4 p1 = __ldg((const float4*)props + var * 2 + 1);
            float pr[NP] = {p0.x, p0.y, p0.z, p0.w, p1.x, p1.y, p1.z, p1.w};
            float accA = __ldg(b2), accB = 0.0f;
            #pragma unroll
            for (int jh = 0; jh < NHID; jh += 4) {
                float s0 = __ldg(b1 + jh),     s1 = __ldg(b1 + jh + 1);
                float s2 = __ldg(b1 + jh + 2), s3 = __ldg(b1 + jh + 3);
                #pragma unroll
                for (int p = 0; p < NP; p++) {
                    float pv = pr[p];
                    const float* w = W1 + p * NHID + jh;
                    s0 = fmaf(pv, __ldg(w),     s0);
                    s1 = fmaf(pv, __ldg(w + 1), s1);
                    s2 = fmaf(pv, __ldg(w + 2), s2);
                    s3 = fmaf(pv, __ldg(w + 3), s3);
                }
                accA = fmaf(fmaxf(s0, 0.0f), __ldg(W2 + jh),     accA);
                accB = fmaf(fmaxf(s1, 0.0f), __ldg(W2 + jh + 1), accB);
                accA = fmaf(fmaxf(s2, 0.0f), __ldg(W2 + jh + 2), accA);
                accB = fmaf(fmaxf(s3, 0.0f), __ldg(W2 + jh + 3), accB);
            }
            sgate[tid] = 1.0f / (1.0f + expf(-(accA + accB)));
        }
    }

    // segment boundary scan (first 65536 global threads, 4 nodes each)
    {
        int gid = b * 512 + tid;
        if (gid < NN / 4) {
            int i0 = gid * 4;
            int4 b4 = *(const int4*)&batch[i0];
            int v[4] = {b4.x, b4.y, b4.z, b4.w};
            int p = (i0 == 0) ? -1 : __ldg(&batch[i0 - 1]);
            #pragma unroll
            for (int e = 0; e < 4; e++) {
                for (int g = p + 1; g <= v[e]; g++) g_start[g] = i0 + e;
                p = v[e];
            }
            if (i0 + 4 == NN)
                for (int g = v[3] + 1; g <= NG; g++) g_start[g] = NN;
        }
    }

    if (tid < 256) sbias[tid] = bpre[tid];

    const int arow = tid >> 3;     // 0..63
    const int aseg = tid & 7;      // float4 slot
    const uint32_t a_sts0 = sbase + A_OFF + (uint32_t)((arow * 264 + aseg * 4) * 2);

    // A prefetch held as half2 (16 regs)
    uint32_t rh[16];
    {
        const float* ap = emb + (size_t)(tstart * 64 + arow) * HH + aseg * 4;
        #pragma unroll
        for (int j = 0; j < 8; j++) {
            float4 a = *(const float4*)(ap + j * 32);
            __half2 h0 = __float22half2_rn(make_float2(a.x, a.y));
            __half2 h1 = __float22half2_rn(make_float2(a.z, a.w));
            rh[2 * j]     = *(uint32_t*)&h0;
            rh[2 * j + 1] = *(uint32_t*)&h1;
        }
    }
    __syncthreads();

    // ---- phase B: A(tstart) STS, brow/wrow(tstart) ----
    #pragma unroll
    for (int j = 0; j < 8; j++) {
        asm volatile("st.shared.v2.b32 [%0], {%1,%2};"
                     :: "r"(a_sts0 + j * 64), "r"(rh[2 * j]), "r"(rh[2 * j + 1]) : "memory");
    }
    if (tid < 64) {
        int m = tstart * 64 + tid;
        brow[tid] = batch[m];
        wrow[tid] = (ntype[m] == 0) ? sgate[tid >> 2] : 1.0f;
    }
    __syncthreads();

    // ldmatrix lane addresses (stride 264 halfs -> conflict-free)
    const uint32_t a_lm = sbase + A_OFF +
        (uint32_t)(((wm * 16 + (lane & 15)) * 264 + (lane >> 4) * 8) * 2);
    const uint32_t b_lm = sbase +
        (uint32_t)(((wn * 64 + (lane >> 4) * 8 + (lane & 7)) * 264 + ((lane >> 3) & 1) * 8) * 2);

    // carry state
    int   carry_g = -1;
    float cs[8][2], cm[8][2];

    auto flush_carry = [&]() {
        #pragma unroll
        for (int ni = 0; ni < 8; ni++) {
            float s0 = cs[ni][0], s1 = cs[ni][1];
            float m0 = cm[ni][0], m1 = cm[ni][1];
            #pragma unroll
            for (int off = 4; off < 32; off <<= 1) {
                s0 += __shfl_xor_sync(0xffffffffu, s0, off);
                s1 += __shfl_xor_sync(0xffffffffu, s1, off);
                m0 = fmaxf(m0, __shfl_xor_sync(0xffffffffu, m0, off));
                m1 = fmaxf(m1, __shfl_xor_sync(0xffffffffu, m1, off));
            }
            if (lane < 4) {
                int c = wn * 64 + ni * 8 + lane * 2;
                atomicAdd(&g_sums[carry_g * HH + c],     s0);
                atomicAdd(&g_sums[carry_g * HH + c + 1], s1);
                atomicMaxF(&g_maxs[carry_g * HH + c],     m0);
                atomicMaxF(&g_maxs[carry_g * HH + c + 1], m1);
            }
        }
    };

    for (int it = 0; it < tcnt; it++) {
        const int cur = it & 1;
        const bool hn = (it + 1 < tcnt);
        const int nt  = tstart + it + 1;

        if (hn) {
            const float* ap = emb + (size_t)(nt * 64 + arow) * HH + aseg * 4;
            #pragma unroll
            for (int j = 0; j < 8; j++) {
                float4 a = *(const float4*)(ap + j * 32);
                __half2 h0 = __float22half2_rn(make_float2(a.x, a.y));
                __half2 h1 = __float22half2_rn(make_float2(a.z, a.w));
                rh[2 * j]     = *(uint32_t*)&h0;
                rh[2 * j + 1] = *(uint32_t*)&h1;
            }
            if (tid < 64) {
                int m = nt * 64 + tid;
                brow[(cur ^ 1) * 64 + tid] = batch[m];
                wrow[(cur ^ 1) * 64 + tid] =
                    (ntype[m] == 0) ? sgate[(it + 1) * 16 + (tid >> 2)] : 1.0f;
            }
        }

        float acc[8][4];
        #pragma unroll
        for (int ni = 0; ni < 8; ni++)
            #pragma unroll
            for (int r = 0; r < 4; r++) acc[ni][r] = 0.0f;

        const uint32_t ab = a_lm + (uint32_t)(cur * A_STAGE);
        #pragma unroll
        for (int ks = 0; ks < 16; ks++) {
            uint32_t af[4];
            LDMX4(af[0], af[1], af[2], af[3], ab + ks * 32);
            uint32_t bf[4][4];
            #pragma unroll
            for (int nip = 0; nip < 4; nip++)
                LDMX4(bf[nip][0], bf[nip][1], bf[nip][2], bf[nip][3],
                      b_lm + nip * 8448 + ks * 32);
            #pragma unroll
            for (int ni = 0; ni < 8; ni++)
                MMA16816(acc[ni][0], acc[ni][1], acc[ni][2], acc[ni][3],
                         af[0], af[1], af[2], af[3],
                         bf[ni >> 1][(ni & 1) * 2], bf[ni >> 1][(ni & 1) * 2 + 1]);
        }

        if (hn) {
            uint32_t base = sbase + A_OFF + (uint32_t)((cur ^ 1) * A_STAGE)
                          + (uint32_t)((arow * 264 + aseg * 4) * 2);
            #pragma unroll
            for (int j = 0; j < 8; j++) {
                asm volatile("st.shared.v2.b32 [%0], {%1,%2};"
                             :: "r"(base + j * 64), "r"(rh[2 * j]), "r"(rh[2 * j + 1]) : "memory");
            }
        }

        // ---- epilogue: bias + gate, carry-based segment reduce ----
        {
            const int l1 = wm * 16 + (lane >> 2);
            const int l2 = l1 + 8;
            const int*   br = brow + cur * 64;
            const float* wr = wrow + cur * 64;
            const float w1 = wr[l1], w2 = wr[l2];
            #pragma unroll
            for (int ni = 0; ni < 8; ni++) {
                int c = wn * 64 + ni * 8 + (lane & 3) * 2;
                float b0 = sbias[c], b1 = sbias[c + 1];
                acc[ni][0] = (acc[ni][0] + b0) * w1;
                acc[ni][1] = (acc[ni][1] + b1) * w1;
                acc[ni][2] = (acc[ni][2] + b0) * w2;
                acc[ni][3] = (acc[ni][3] + b1) * w2;
            }
            const int gtop = br[wm * 16];
            const int gbot = br[wm * 16 + 15];
            if (gtop == gbot) {
                if (gtop == carry_g) {
                    #pragma unroll
                    for (int ni = 0; ni < 8; ni++) {
                        cs[ni][0] += acc[ni][0] + acc[ni][2];
                        cs[ni][1] += acc[ni][1] + acc[ni][3];
                        cm[ni][0] = fmaxf(cm[ni][0], fmaxf(acc[ni][0], acc[ni][2]));
                        cm[ni][1] = fmaxf(cm[ni][1], fmaxf(acc[ni][1], acc[ni][3]));
                    }
                } else {
                    if (carry_g >= 0) flush_carry();
                    carry_g = gtop;
                    #pragma unroll
                    for (int ni = 0; ni < 8; ni++) {
                        cs[ni][0] = acc[ni][0] + acc[ni][2];
                        cs[ni][1] = acc[ni][1] + acc[ni][3];
                        cm[ni][0] = fmaxf(acc[ni][0], acc[ni][2]);
                        cm[ni][1] = fmaxf(acc[ni][1], acc[ni][3]);
                    }
                }
            } else {
                if (carry_g >= 0) flush_carry();
                carry_g = -1;
                const int bg1 = br[l1], bg2 = br[l2];
                for (int g = gtop; g <= gbot; g++) {
                    const bool p1 = (bg1 == g), p2 = (bg2 == g);
                    #pragma unroll
                    for (int ni = 0; ni < 8; ni++) {
                        float s0 = (p1 ? acc[ni][0] : 0.0f) + (p2 ? acc[ni][2] : 0.0f);
                        float s1 = (p1 ? acc[ni][1] : 0.0f) + (p2 ? acc[ni][3] : 0.0f);
                        float m0v = fmaxf(p1 ? acc[ni][0] : -INFINITY, p2 ? acc[ni][2] : -INFINITY);
                        float m1v = fmaxf(p1 ? acc[ni][1] : -INFINITY, p2 ? acc[ni][3] : -INFINITY);
                        #pragma unroll
                        for (int off = 4; off < 32; off <<= 1) {
                            s0  += __shfl_xor_sync(0xffffffffu, s0,  off);
                            s1  += __shfl_xor_sync(0xffffffffu, s1,  off);
                            m0v = fmaxf(m0v, __shfl_xor_sync(0xffffffffu, m0v, off));
                            m1v = fmaxf(m1v, __shfl_xor_sync(0xffffffffu, m1v, off));
                        }
                        if (lane < 4) {
                            int c = wn * 64 + ni * 8 + lane * 2;
                            atomicAdd(&g_sums[g * HH + c],     s0);
                            atomicAdd(&g_sums[g * HH + c + 1], s1);
                            if (m0v > -INFINITY) atomicMaxF(&g_maxs[g * HH + c],     m0v);
                            if (m1v > -INFINITY) atomicMaxF(&g_maxs[g * HH + c + 1], m1v);
                        }
                    }
                }
            }
        }
        __syncthreads();
    }

    if (carry_g >= 0) flush_carry();
}

// ---------------- final linear v4: 3-stage ring, 1 sync/tile, cp-before-compute ----------------
// dyn smem: sw 3 x (32 x 256 f) = 98304 | combT [512][4] f = 8192  -> 106496 B
#define FK_SMEM 106496

__global__ __launch_bounds__(256) void final_kernel(
    const float* __restrict__ Wpost,
    const float* __restrict__ bpost,
    float* __restrict__ out)
{
    extern __shared__ char fsm[];
    float* swf   = (float*)fsm;                 // [3][32][256]
    float* combT = (float*)(fsm + 98304);       // [512][4]
    const uint32_t sbase = smem_u32(fsm);

    const int tid = threadIdx.x;
    const int g0  = blockIdx.x * 4;

    // prologue: stage W k-tiles 0 and 1 into ring slots 0,1
    #pragma unroll
    for (int s = 0; s < 2; s++) {
        #pragma unroll
        for (int i = 0; i < 8; i++) {
            int u = tid + i * 256;
            cp16(sbase + (uint32_t)(s * 32768) + (uint32_t)((u >> 6) * 1024 + (u & 63) * 16),
                 Wpost + (size_t)(s * 32 + (u >> 6)) * 256 + (u & 63) * 4);
        }
        asm volatile("cp.async.commit_group;" ::: "memory");
    }

    // fill combT[k][g] (invc computed inline); visible after first sync in the loop
    for (int idx = tid; idx < 2048; idx += 256) {
        int k = idx >> 2, g = idx & 3;
        int gg = g0 + g;
        float v;
        if (k < HH) {
            float cnt = (float)(g_start[gg + 1] - g_start[gg]);
            v = g_sums[(size_t)gg * HH + k] / fmaxf(cnt, 1.0f);
        } else {
            float m = g_maxs[(size_t)gg * HH + (k - HH)];
            v = isfinite(m) ? m : 0.0f;
        }
        combT[idx] = v;
    }

    const int c = tid;
    float a0 = 0.0f, a1 = 0.0f, a2 = 0.0f, a3 = 0.0f;

    for (int t = 0; t < 16; t++) {
        if (t < 15) { asm volatile("cp.async.wait_group 1;" ::: "memory"); }
        else        { asm volatile("cp.async.wait_group 0;" ::: "memory"); }
        __syncthreads();   // tile t visible; stage (t-1)%3 free for overwrite; combT visible (t=0)

        // issue cp for tile t+2 into ring slot (t+2)%3 BEFORE compute
        if (t + 2 < 16) {
            uint32_t dst = sbase + (uint32_t)(((t + 2) % 3) * 32768);
            const float* src = Wpost + (size_t)(t + 2) * 32 * 256;
            #pragma unroll
            for (int i = 0; i < 8; i++) {
                int u = tid + i * 256;
                cp16(dst + (uint32_t)((u >> 6) * 1024 + (u & 63) * 16),
                     src + (size_t)(u >> 6) * 256 + (u & 63) * 4);
            }
            asm volatile("cp.async.commit_group;" ::: "memory");
        }

        const float* wb = swf + (t % 3) * 8192;
        #pragma unroll
        for (int kk = 0; kk < 32; kk++) {
            float4 cb = *(const float4*)&combT[(t * 32 + kk) * 4];
            float w = wb[kk * 256 + c];
            a0 = fmaf(cb.x, w, a0);
            a1 = fmaf(cb.y, w, a1);
            a2 = fmaf(cb.z, w, a2);
            a3 = fmaf(cb.w, w, a3);
        }
    }

    float bb = bpost[c];
    out[(size_t)(g0 + 0) * HH + c] = a0 + bb;
    out[(size_t)(g0 + 1) * HH + c] = a1 + bb;
    out[(size_t)(g0 + 2) * HH + c] = a2 + bb;
    out[(size_t)(g0 + 3) * HH + c] = a3 + bb;
}

// ---------------- launch ----------------
extern "C" void kernel_launch(void* const* d_in, const int* in_sizes, int n_in,
                              void* d_out, int out_size)
{
    const float* emb   = (const float*)d_in[0];
    const int*   batch = (const int*)  d_in[1];
    const float* props = (const float*)d_in[2];
    const int*   ntype = (const int*)  d_in[3];
    const float* Wpre  = (const float*)d_in[4];
    const float* bpre  = (const float*)d_in[5];
    const float* W1    = (const float*)d_in[6];
    const float* b1    = (const float*)d_in[7];
    const float* W2    = (const float*)d_in[8];
    const float* b2    = (const float*)d_in[9];
    const float* Wpost = (const float*)d_in[10];
    const float* bpost = (const float*)d_in[11];
    float* out = (float*)d_out;

    cudaFuncSetAttribute(main_kernel, cudaFuncAttributeMaxDynamicSharedMemorySize, SMEM_SZ);
    cudaFuncSetAttribute(final_kernel, cudaFuncAttributeMaxDynamicSharedMemorySize, FK_SMEM);

    void* p_sums = nullptr;
    void* p_maxs = nullptr;
    cudaGetSymbolAddress(&p_sums, g_sums);
    cudaGetSymbolAddress(&p_maxs, g_maxs);
    cudaMemsetAsync(p_sums, 0x00, NG * HH * sizeof(float));
    cudaMemsetAsync(p_maxs, 0xFF, NG * HH * sizeof(float));   // NaN -> acts as -inf for our atomics

    main_kernel<<<GRID_MAIN, 512, SMEM_SZ>>>(emb, batch, ntype, bpre, Wpre,
                                             props, W1, b1, W2, b2);
    final_kernel<<<NG / 4, 256, FK_SMEM>>>(Wpost, bpost, out);
}

// round 16
// speedup vs baseline: 1.0104x; 1.0104x over previous
#include <cuda_runtime.h>
#include <cuda_fp16.h>
#include <math.h>
#include <stdint.h>

#define NN   262144
#define HH   256
#define NV   65536
#define NG   512
#define NP   8
#define NHID 64

#define NTILES    4096      // NN / 64
#define GRID_MAIN 148

// ---------------- device globals ----------------
__device__ float  g_sums[NG * HH];
__device__ float  g_maxs[NG * HH];
__device__ int    g_start[NG + 1];

// ---------------- helpers ----------------
__device__ __forceinline__ uint32_t smem_u32(const void* p) {
    uint32_t a;
    asm("{ .reg .u64 t; cvta.to.shared.u64 t, %1; cvt.u32.u64 %0, t; }" : "=r"(a) : "l"(p));
    return a;
}
__device__ __forceinline__ void cp16(uint32_t dst, const void* src) {
    asm volatile("cp.async.cg.shared.global [%0], [%1], 16;" :: "r"(dst), "l"(src));
}
__device__ __forceinline__ void atomicMaxF(float* addr, float v) {
    if (v >= 0.0f) atomicMax((int*)addr, __float_as_int(v));
    else           atomicMin((unsigned int*)addr, __float_as_uint(v));
}
#define LDMX4(r0,r1,r2,r3,addr) \
    asm volatile("ldmatrix.sync.aligned.m8n8.x4.shared.b16 {%0,%1,%2,%3}, [%4];" \
                 : "=r"(r0), "=r"(r1), "=r"(r2), "=r"(r3) : "r"(addr))
#define MMA16816(c0,c1,c2,c3,a0,a1,a2,a3,b0,b1) \
    asm volatile("mma.sync.aligned.m16n8k16.row.col.f32.f16.f16.f32 " \
                 "{%0,%1,%2,%3}, {%4,%5,%6,%7}, {%8,%9}, {%0,%1,%2,%3};" \
                 : "+f"(c0), "+f"(c1), "+f"(c2), "+f"(c3) \
                 : "r"(a0), "r"(a1), "r"(a2), "r"(a3), "r"(b0), "r"(b1))

// ---------------- main: persistent HMMA GEMM; contiguous tiles; carry epilogue ----------------
// smem layout (206848 B dynamic):
//   B:        [0, 135168)                256 rows x 264 halfs (stride 528 B)
//   A stages: [135168, 135168+2*33792)   2 x (64 rows x 264 halfs)
//   misc at 202752:
//     brow[2][64] int (512) | wrow[2][64] f (512) | sbias[256] f (1024) | sgate[448] f (1792)
#define A_OFF    135168
#define A_STAGE  33792
#define MISC_OFF 202752
#define SMEM_SZ  206848

__global__ __launch_bounds__(512, 1) void main_kernel(
    const float* __restrict__ emb,
    const int*   __restrict__ batch,
    const int*   __restrict__ ntype,
    const float* __restrict__ bpre,
    const float* __restrict__ Wpre,
    const float* __restrict__ props,
    const float* __restrict__ W1, const float* __restrict__ b1,
    const float* __restrict__ W2, const float* __restrict__ b2)
{
    extern __shared__ char sm[];
    const uint32_t sbase = smem_u32(sm);
    int*   brow  = (int*)  (sm + MISC_OFF);            // [2][64]
    float* wrow  = (float*)(sm + MISC_OFF + 512);      // [2][64]
    float* sbias = (float*)(sm + MISC_OFF + 1024);     // [256]
    float* sgate = (float*)(sm + MISC_OFF + 2048);     // [448]

    const int tid  = threadIdx.x;
    const int wid  = tid >> 5;
    const int lane = tid & 31;
    const int wm   = wid >> 2;     // 0..3: rows [wm*16, +16)
    const int wn   = wid & 3;      // 0..3: cols [wn*64, +64)
    const int b    = blockIdx.x;

    // contiguous tile range: blocks 0..99 get 28 tiles, 100..147 get 27
    const int tstart = b * 27 + min(b, 100);
    const int tcnt   = 27 + (b < 100 ? 1 : 0);

    // ---- phase A: B transpose+convert, gates, g_start scan, sbias, A(tstart) LDG ----

    // B: Wpre[k][n] -> Bs[n][k] fp16 (coalesced LDG.32 across n at fixed k)
    {
        const int bn  = tid & 255;       // output row n
        const int bk0 = (tid >> 8) * 128;
        const uint32_t bdst = sbase + (uint32_t)(bn * 528 + bk0 * 2);
        #pragma unroll
        for (int jj = 0; jj < 16; jj++) {
            float v[8];
            #pragma unroll
            for (int i = 0; i < 8; i++)
                v[i] = __ldg(&Wpre[(size_t)(bk0 + jj * 8 + i) * 256 + bn]);
            __half2 q0 = __float22half2_rn(make_float2(v[0], v[1]));
            __half2 q1 = __float22half2_rn(make_float2(v[2], v[3]));
            __half2 q2 = __float22half2_rn(make_float2(v[4], v[5]));
            __half2 q3 = __float22half2_rn(make_float2(v[6], v[7]));
            asm volatile("st.shared.v4.b32 [%0], {%1,%2,%3,%4};"
                         :: "r"(bdst + jj * 16),
                            "r"(*(uint32_t*)&q0), "r"(*(uint32_t*)&q1),
                            "r"(*(uint32_t*)&q2), "r"(*(uint32_t*)&q3) : "memory");
        }
    }

    // gates for this CTA's contiguous var range
    {
        if (tid < tcnt * 16) {
            const int var = tstart * 16 + tid;
            float4 p0 = __ldg((const float4*)props + var * 2);
            float4 p1 = __ldg((const float4*)props + var * 2 + 1);
            float pr[NP] = {p0.x, p0.y, p0.z, p0.w, p1.x, p1.y, p1.z, p1.w};
            float accA = __ldg(b2), accB = 0.0f;
            #pragma unroll
            for (int jh = 0; jh < NHID; jh += 4) {
                float s0 = __ldg(b1 + jh),     s1 = __ldg(b1 + jh + 1);
                float s2 = __ldg(b1 + jh + 2), s3 = __ldg(b1 + jh + 3);
                #pragma unroll
                for (int p = 0; p < NP; p++) {
                    float pv = pr[p];
                    const float* w = W1 + p * NHID + jh;
                    s0 = fmaf(pv, __ldg(w),     s0);
                    s1 = fmaf(pv, __ldg(w + 1), s1);
                    s2 = fmaf(pv, __ldg(w + 2), s2);
                    s3 = fmaf(pv, __ldg(w + 3), s3);
                }
                accA = fmaf(fmaxf(s0, 0.0f), __ldg(W2 + jh),     accA);
                accB = fmaf(fmaxf(s1, 0.0f), __ldg(W2 + jh + 1), accB);
                accA = fmaf(fmaxf(s2, 0.0f), __ldg(W2 + jh + 2), accA);
                accB = fmaf(fmaxf(s3, 0.0f), __ldg(W2 + jh + 3), accB);
            }
            sgate[tid] = 1.0f / (1.0f + expf(-(accA + accB)));
        }
    }

    // segment boundary scan (first 65536 global threads, 4 nodes each)
    {
        int gid = b * 512 + tid;
        if (gid < NN / 4) {
            int i0 = gid * 4;
            int4 b4 = *(const int4*)&batch[i0];
            int v[4] = {b4.x, b4.y, b4.z, b4.w};
            int p = (i0 == 0) ? -1 : __ldg(&batch[i0 - 1]);
            #pragma unroll
            for (int e = 0; e < 4; e++) {
                for (int g = p + 1; g <= v[e]; g++) g_start[g] = i0 + e;
                p = v[e];
            }
            if (i0 + 4 == NN)
                for (int g = v[3] + 1; g <= NG; g++) g_start[g] = NN;
        }
    }

    if (tid < 256) sbias[tid] = bpre[tid];

    const int arow = tid >> 3;     // 0..63
    const int aseg = tid & 7;      // float4 slot
    const uint32_t a_sts0 = sbase + A_OFF + (uint32_t)((arow * 264 + aseg * 4) * 2);

    // A prefetch held as half2 (16 regs)
    uint32_t rh[16];
    {
        const float* ap = emb + (size_t)(tstart * 64 + arow) * HH + aseg * 4;
        #pragma unroll
        for (int j = 0; j < 8; j++) {
            float4 a = *(const float4*)(ap + j * 32);
            __half2 h0 = __float22half2_rn(make_float2(a.x, a.y));
            __half2 h1 = __float22half2_rn(make_float2(a.z, a.w));
            rh[2 * j]     = *(uint32_t*)&h0;
            rh[2 * j + 1] = *(uint32_t*)&h1;
        }
    }
    __syncthreads();

    // ---- phase B: A(tstart) STS, brow/wrow(tstart) ----
    #pragma unroll
    for (int j = 0; j < 8; j++) {
        asm volatile("st.shared.v2.b32 [%0], {%1,%2};"
                     :: "r"(a_sts0 + j * 64), "r"(rh[2 * j]), "r"(rh[2 * j + 1]) : "memory");
    }
    if (tid < 64) {
        int m = tstart * 64 + tid;
        brow[tid] = batch[m];
        wrow[tid] = (ntype[m] == 0) ? sgate[tid >> 2] : 1.0f;
    }
    __syncthreads();

    // ldmatrix lane addresses (stride 264 halfs -> conflict-free)
    const uint32_t a_lm = sbase + A_OFF +
        (uint32_t)(((wm * 16 + (lane & 15)) * 264 + (lane >> 4) * 8) * 2);
    const uint32_t b_lm = sbase +
        (uint32_t)(((wn * 64 + (lane >> 4) * 8 + (lane & 7)) * 264 + ((lane >> 3) & 1) * 8) * 2);

    // carry state
    int   carry_g = -1;
    float cs[8][2], cm[8][2];

    auto flush_carry = [&]() {
        #pragma unroll
        for (int ni = 0; ni < 8; ni++) {
            float s0 = cs[ni][0], s1 = cs[ni][1];
            float m0 = cm[ni][0], m1 = cm[ni][1];
            #pragma unroll
            for (int off = 4; off < 32; off <<= 1) {
                s0 += __shfl_xor_sync(0xffffffffu, s0, off);
                s1 += __shfl_xor_sync(0xffffffffu, s1, off);
                m0 = fmaxf(m0, __shfl_xor_sync(0xffffffffu, m0, off));
                m1 = fmaxf(m1, __shfl_xor_sync(0xffffffffu, m1, off));
            }
            if (lane < 4) {
                int c = wn * 64 + ni * 8 + lane * 2;
                atomicAdd(&g_sums[carry_g * HH + c],     s0);
                atomicAdd(&g_sums[carry_g * HH + c + 1], s1);
                atomicMaxF(&g_maxs[carry_g * HH + c],     m0);
                atomicMaxF(&g_maxs[carry_g * HH + c + 1], m1);
            }
        }
    };

    for (int it = 0; it < tcnt; it++) {
        const int cur = it & 1;
        const bool hn = (it + 1 < tcnt);
        const int nt  = tstart + it + 1;

        if (hn) {
            const float* ap = emb + (size_t)(nt * 64 + arow) * HH + aseg * 4;
            #pragma unroll
            for (int j = 0; j < 8; j++) {
                float4 a = *(const float4*)(ap + j * 32);
                __half2 h0 = __float22half2_rn(make_float2(a.x, a.y));
                __half2 h1 = __float22half2_rn(make_float2(a.z, a.w));
                rh[2 * j]     = *(uint32_t*)&h0;
                rh[2 * j + 1] = *(uint32_t*)&h1;
            }
            if (tid < 64) {
                int m = nt * 64 + tid;
                brow[(cur ^ 1) * 64 + tid] = batch[m];
                wrow[(cur ^ 1) * 64 + tid] =
                    (ntype[m] == 0) ? sgate[(it + 1) * 16 + (tid >> 2)] : 1.0f;
            }
        }

        float acc[8][4];
        #pragma unroll
        for (int ni = 0; ni < 8; ni++)
            #pragma unroll
            for (int r = 0; r < 4; r++) acc[ni][r] = 0.0f;

        const uint32_t ab = a_lm + (uint32_t)(cur * A_STAGE);
        #pragma unroll
        for (int ks = 0; ks < 16; ks++) {
            uint32_t af[4];
            LDMX4(af[0], af[1], af[2], af[3], ab + ks * 32);
            uint32_t bf[4][4];
            #pragma unroll
            for (int nip = 0; nip < 4; nip++)
                LDMX4(bf[nip][0], bf[nip][1], bf[nip][2], bf[nip][3],
                      b_lm + nip * 8448 + ks * 32);
            #pragma unroll
            for (int ni = 0; ni < 8; ni++)
                MMA16816(acc[ni][0], acc[ni][1], acc[ni][2], acc[ni][3],
                         af[0], af[1], af[2], af[3],
                         bf[ni >> 1][(ni & 1) * 2], bf[ni >> 1][(ni & 1) * 2 + 1]);
        }

        if (hn) {
            uint32_t base = sbase + A_OFF + (uint32_t)((cur ^ 1) * A_STAGE)
                          + (uint32_t)((arow * 264 + aseg * 4) * 2);
            #pragma unroll
            for (int j = 0; j < 8; j++) {
                asm volatile("st.shared.v2.b32 [%0], {%1,%2};"
                             :: "r"(base + j * 64), "r"(rh[2 * j]), "r"(rh[2 * j + 1]) : "memory");
            }
        }

        // ---- epilogue: bias + gate, carry-based segment reduce ----
        {
            const int l1 = wm * 16 + (lane >> 2);
            const int l2 = l1 + 8;
            const int*   br = brow + cur * 64;
            const float* wr = wrow + cur * 64;
            const float w1 = wr[l1], w2 = wr[l2];
            #pragma unroll
            for (int ni = 0; ni < 8; ni++) {
                int c = wn * 64 + ni * 8 + (lane & 3) * 2;
                float b0 = sbias[c], b1 = sbias[c + 1];
                acc[ni][0] = (acc[ni][0] + b0) * w1;
                acc[ni][1] = (acc[ni][1] + b1) * w1;
                acc[ni][2] = (acc[ni][2] + b0) * w2;
                acc[ni][3] = (acc[ni][3] + b1) * w2;
            }
            const int gtop = br[wm * 16];
            const int gbot = br[wm * 16 + 15];
            if (gtop == gbot) {
                if (gtop == carry_g) {
                    #pragma unroll
                    for (int ni = 0; ni < 8; ni++) {
                        cs[ni][0] += acc[ni][0] + acc[ni][2];
                        cs[ni][1] += acc[ni][1] + acc[ni][3];
                        cm[ni][0] = fmaxf(cm[ni][0], fmaxf(acc[ni][0], acc[ni][2]));
                        cm[ni][1] = fmaxf(cm[ni][1], fmaxf(acc[ni][1], acc[ni][3]));
                    }
                } else {
                    if (carry_g >= 0) flush_carry();
                    carry_g = gtop;
                    #pragma unroll
                    for (int ni = 0; ni < 8; ni++) {
                        cs[ni][0] = acc[ni][0] + acc[ni][2];
                        cs[ni][1] = acc[ni][1] + acc[ni][3];
                        cm[ni][0] = fmaxf(acc[ni][0], acc[ni][2]);
                        cm[ni][1] = fmaxf(acc[ni][1], acc[ni][3]);
                    }
                }
            } else {
                if (carry_g >= 0) flush_carry();
                carry_g = -1;
                const int bg1 = br[l1], bg2 = br[l2];
                for (int g = gtop; g <= gbot; g++) {
                    const bool p1 = (bg1 == g), p2 = (bg2 == g);
                    #pragma unroll
                    for (int ni = 0; ni < 8; ni++) {
                        float s0 = (p1 ? acc[ni][0] : 0.0f) + (p2 ? acc[ni][2] : 0.0f);
                        float s1 = (p1 ? acc[ni][1] : 0.0f) + (p2 ? acc[ni][3] : 0.0f);
                        float m0v = fmaxf(p1 ? acc[ni][0] : -INFINITY, p2 ? acc[ni][2] : -INFINITY);
                        float m1v = fmaxf(p1 ? acc[ni][1] : -INFINITY, p2 ? acc[ni][3] : -INFINITY);
                        #pragma unroll
                        for (int off = 4; off < 32; off <<= 1) {
                            s0  += __shfl_xor_sync(0xffffffffu, s0,  off);
                            s1  += __shfl_xor_sync(0xffffffffu, s1,  off);
                            m0v = fmaxf(m0v, __shfl_xor_sync(0xffffffffu, m0v, off));
                            m1v = fmaxf(m1v, __shfl_xor_sync(0xffffffffu, m1v, off));
                        }
                        if (lane < 4) {
                            int c = wn * 64 + ni * 8 + lane * 2;
                            atomicAdd(&g_sums[g * HH + c],     s0);
                            atomicAdd(&g_sums[g * HH + c + 1], s1);
                            if (m0v > -INFINITY) atomicMaxF(&g_maxs[g * HH + c],     m0v);
                            if (m1v > -INFINITY) atomicMaxF(&g_maxs[g * HH + c + 1], m1v);
                        }
                    }
                }
            }
        }
        __syncthreads();
    }

    if (carry_g >= 0) flush_carry();
}

// ---------------- final linear v5: 512 threads, parity k-split, 4 graphs in regs ----------------
// dyn smem: sw 3 x (32 x 256 f) = 98304 | combT [512][4] f = 8192  -> 106496 B
// reduction reuses swf area after compute.
#define FK_SMEM 106496

__global__ __launch_bounds__(512) void final_kernel(
    const float* __restrict__ Wpost,
    const float* __restrict__ bpost,
    float* __restrict__ out)
{
    extern __shared__ char fsm[];
    float* swf   = (float*)fsm;                 // [3][32][256]
    float* combT = (float*)(fsm + 98304);       // [512][4]
    float* red   = (float*)fsm;                 // reuse: [2][256][4]
    const uint32_t sbase = smem_u32(fsm);

    const int tid = threadIdx.x;
    const int c   = tid & 255;
    const int h   = tid >> 8;       // parity group: computes tiles with (t&1)==h
    const int g0  = blockIdx.x * 4;

    // prologue: stage W k-tiles 0 and 1 into ring slots 0,1 (4 cp16/thread each)
    #pragma unroll
    for (int s = 0; s < 2; s++) {
        #pragma unroll
        for (int i = 0; i < 4; i++) {
            int u = tid + i * 512;
            cp16(sbase + (uint32_t)(s * 32768) + (uint32_t)((u >> 6) * 1024 + (u & 63) * 16),
                 Wpost + (size_t)(s * 32 + (u >> 6)) * 256 + (u & 63) * 4);
        }
        asm volatile("cp.async.commit_group;" ::: "memory");
    }

    // fill combT[k][g] (invc inline)
    for (int idx = tid; idx < 2048; idx += 512) {
        int k = idx >> 2, g = idx & 3;
        int gg = g0 + g;
        float v;
        if (k < HH) {
            float cnt = (float)(g_start[gg + 1] - g_start[gg]);
            v = g_sums[(size_t)gg * HH + k] / fmaxf(cnt, 1.0f);
        } else {
            float m = g_maxs[(size_t)gg * HH + (k - HH)];
            v = isfinite(m) ? m : 0.0f;
        }
        combT[idx] = v;
    }

    float a0 = 0.0f, a1 = 0.0f, a2 = 0.0f, a3 = 0.0f;

    for (int t = 0; t < 16; t++) {
        if (t < 15) { asm volatile("cp.async.wait_group 1;" ::: "memory"); }
        else        { asm volatile("cp.async.wait_group 0;" ::: "memory"); }
        __syncthreads();   // tile t visible; slot (t-1)%3 free; combT visible (t=0)

        // issue cp for tile t+2 BEFORE compute
        if (t + 2 < 16) {
            uint32_t dst = sbase + (uint32_t)(((t + 2) % 3) * 32768);
            const float* src = Wpost + (size_t)(t + 2) * 32 * 256;
            #pragma unroll
            for (int i = 0; i < 4; i++) {
                int u = tid + i * 512;
                cp16(dst + (uint32_t)((u >> 6) * 1024 + (u & 63) * 16),
                     src + (size_t)(u >> 6) * 256 + (u & 63) * 4);
            }
            asm volatile("cp.async.commit_group;" ::: "memory");
        }

        if ((t & 1) == h) {
            const float* wb = swf + (t % 3) * 8192;
            #pragma unroll
            for (int kk = 0; kk < 32; kk++) {
                float4 cb = *(const float4*)&combT[(t * 32 + kk) * 4];
                float w = wb[kk * 256 + c];
                a0 = fmaf(cb.x, w, a0);
                a1 = fmaf(cb.y, w, a1);
                a2 = fmaf(cb.z, w, a2);
                a3 = fmaf(cb.w, w, a3);
            }
        }
    }

    // combine the two parity groups' partials via smem
    __syncthreads();   // all compute done; swf area reusable
    red[(h * 256 + c) * 4 + 0] = a0;
    red[(h * 256 + c) * 4 + 1] = a1;
    red[(h * 256 + c) * 4 + 2] = a2;
    red[(h * 256 + c) * 4 + 3] = a3;
    __syncthreads();
    if (h == 0) {
        float4 other = *(const float4*)&red[(256 + c) * 4];
        float bb = bpost[c];
        out[(size_t)(g0 + 0) * HH + c] = a0 + other.x + bb;
        out[(size_t)(g0 + 1) * HH + c] = a1 + other.y + bb;
        out[(size_t)(g0 + 2) * HH + c] = a2 + other.z + bb;
        out[(size_t)(g0 + 3) * HH + c] = a3 + other.w + bb;
    }
}

// ---------------- launch ----------------
extern "C" void kernel_launch(void* const* d_in, const int* in_sizes, int n_in,
                              void* d_out, int out_size)
{
    const float* emb   = (const float*)d_in[0];
    const int*   batch = (const int*)  d_in[1];
    const float* props = (const float*)d_in[2];
    const int*   ntype = (const int*)  d_in[3];
    const float* Wpre  = (const float*)d_in[4];
    const float* bpre  = (const float*)d_in[5];
    const float* W1    = (const float*)d_in[6];
    const float* b1    = (const float*)d_in[7];
    const float* W2    = (const float*)d_in[8];
    const float* b2    = (const float*)d_in[9];
    const float* Wpost = (const float*)d_in[10];
    const float* bpost = (const float*)d_in[11];
    float* out = (float*)d_out;

    cudaFuncSetAttribute(main_kernel, cudaFuncAttributeMaxDynamicSharedMemorySize, SMEM_SZ);
    cudaFuncSetAttribute(final_kernel, cudaFuncAttributeMaxDynamicSharedMemorySize, FK_SMEM);

    void* p_sums = nullptr;
    void* p_maxs = nullptr;
    cudaGetSymbolAddress(&p_sums, g_sums);
    cudaGetSymbolAddress(&p_maxs, g_maxs);
    cudaMemsetAsync(p_sums, 0x00, NG * HH * sizeof(float));
    cudaMemsetAsync(p_maxs, 0xFF, NG * HH * sizeof(float));   // NaN -> acts as -inf for our atomics

    main_kernel<<<GRID_MAIN, 512, SMEM_SZ>>>(emb, batch, ntype, bpre, Wpre,
                                             props, W1, b1, W2, b2);
    final_kernel<<<NG / 4, 512, FK_SMEM>>>(Wpost, bpost, out);
}